// round 9
// baseline (speedup 1.0000x reference)
#include <cuda_runtime.h>

// CapsuleLayer dynamic routing, multi-kernel factored form v4.
// X[B=128, I=1152, J=128], W[J=128, K=32, D=32], out V[B=128, K=32, D=32]
//  k_colsum: it0 column-sum partials
//  k1      : per (k, 16 batches): y -> s -> squash -> T / out, W tile in smem
//  k2      : per (split, b): 6 chunks x 64 i, two independent 128-thread groups;
//            GEMM2 -> exp(+sum) -> GEMM1 with inv folded into x (3 group barriers)

#define BB 128
#define II 1152
#define JJ 128
#define KK 32
#define DD 32
#define KD 1024
#define NSPLIT 3
#define ILEN 384
#define CI 64
#define NCH 6
#define C2P 68           // c2 pitch: [0,64) dup-exps, [64,68) partial sums
#define NYP (NSPLIT*2)

typedef unsigned long long u64;

#define FMA2(d,a,b,c) asm("fma.rn.f32x2 %0, %1, %2, %3;" : "=l"(d) : "l"(a), "l"(b), "l"(c))
#define ADD2(d,a,b)   asm("add.rn.f32x2 %0, %1, %2;" : "=l"(d) : "l"(a), "l"(b))
#define MUL2(d,a,b)   asm("mul.rn.f32x2 %0, %1, %2;" : "=l"(d) : "l"(a), "l"(b))
#define PACK2(d,s)    asm("mov.b64 %0, {%1, %1};" : "=l"(d) : "r"(__float_as_uint(s)))
#define GBAR(id)      asm volatile("bar.sync %0, 128;" :: "r"(id) : "memory")

__device__ float g_bl[(size_t)BB * KK * II];            // [b][k][i]
__device__ float g_T[(size_t)BB * KK * JJ];             // [b][k][j]
__device__ float g_yp[(size_t)BB * NYP * KK * JJ];      // [b][slot][k][j]
__device__ float g_ycol[(size_t)BB * 4 * JJ];           // [b][p][j]

// ===================== k_colsum: it0 column sums =====================
__global__ __launch_bounds__(256)
void k_colsum(const float* __restrict__ X)
{
    __shared__ ulonglong2 sred[256];
    const int p = blockIdx.x, b = blockIdx.y;
    const int t = threadIdx.x, j4 = t & 31, ih = t >> 5;
    const float* xp = X + (size_t)b * (II * JJ) + (size_t)(p * 288 + ih * 36) * JJ + j4 * 4;
    u64 s0 = 0, s1 = 0;
    #pragma unroll 4
    for (int ii = 0; ii < 36; ++ii) {
        ulonglong2 v = *(const ulonglong2*)(xp + (size_t)ii * JJ);
        ADD2(s0, s0, v.x); ADD2(s1, s1, v.y);
    }
    sred[ih * 32 + j4] = make_ulonglong2(s0, s1);
    __syncthreads();
    if (t < 32) {
        u64 a0 = 0, a1 = 0;
        #pragma unroll
        for (int h = 0; h < 8; ++h) {
            ulonglong2 v = sred[h * 32 + t];
            ADD2(a0, a0, v.x); ADD2(a1, a1, v.y);
        }
        ((ulonglong2*)(g_ycol + (size_t)(b * 4 + p) * JJ))[t] = make_ulonglong2(a0, a1);
    }
}

// ===================== k1: y -> s -> v -> T / out  (one k, 16 batches) =====================
__global__ __launch_bounds__(256)
void k1_svt(const float* __restrict__ W, float* __restrict__ out, int mode)
{
    __shared__ float wsm[JJ * 33];      // W[:,k,:], padded
    __shared__ float ym[16 * JJ];       // y[bb][j] for this k
    __shared__ float svs[16 * DD];

    const int k = blockIdx.x, bq = blockIdx.y;
    const int t = threadIdx.x, lane = t & 31, w8 = t >> 5;

    // stage W[:,k,:] (coalesced over d)
    #pragma unroll
    for (int ee = 0; ee < 16; ++ee) {
        const int idx = t + ee * 256;            // j*32 + d
        const int j = idx >> 5, d = idx & 31;
        wsm[j * 33 + d] = W[(size_t)j * KD + k * DD + d];
    }
    // phase A: y per batch
    if (mode == 0) {
        #pragma unroll
        for (int ee = 0; ee < 8; ++ee) {
            const int e = t + ee * 256;          // bb*128 + j
            const int bb = e >> 7, j = e & 127;
            const float* yc = g_ycol + (size_t)(bq * 16 + bb) * 4 * JJ;
            ym[e] = (yc[j] + yc[128 + j] + yc[256 + j] + yc[384 + j]) * (1.0f / 32.0f);
        }
    } else {
        #pragma unroll
        for (int ee = 0; ee < 8; ++ee) {
            const int e = t + ee * 256;
            const int bb = e >> 7, j = e & 127;
            const size_t base = (size_t)(bq * 16 + bb) * NYP * KK * JJ + (size_t)k * JJ + j;
            float acc = 0.f;
            #pragma unroll
            for (int s = 0; s < NYP; ++s)
                acc += g_yp[base + (size_t)s * KK * JJ];
            ym[e] = acc;
        }
    }
    __syncthreads();

    // phase B: s[bb][d] for bb = w8 and w8+8, d = lane
    #pragma unroll
    for (int half = 0; half < 2; ++half) {
        const int bb = w8 + half * 8;
        const float* yr = ym + bb * JJ;
        float s = 0.f;
        #pragma unroll 8
        for (int j = 0; j < JJ; ++j)
            s = fmaf(yr[j], wsm[j * 33 + lane], s);
        float ss = s * s;
        #pragma unroll
        for (int off = 16; off > 0; off >>= 1)
            ss += __shfl_xor_sync(0xffffffffu, ss, off);
        const float v = s * (ss / (1.0f + ss) * rsqrtf(ss + 1e-7f));
        if (mode == 2) out[(size_t)(bq * 16 + bb) * KK * DD + k * DD + lane] = v;
        else           svs[bb * DD + lane] = v;
    }
    if (mode == 2) return;
    __syncthreads();

    // phase C: T[bb][j] = sum_d v[bb][d] wsm[j][d]
    const int j = t & 127, bh = t >> 7;
    #pragma unroll
    for (int pass = 0; pass < 8; ++pass) {
        const int bb = pass * 2 + bh;
        float acc = 0.f;
        #pragma unroll 8
        for (int d = 0; d < DD; ++d)
            acc = fmaf(svs[bb * DD + d], wsm[j * 33 + d], acc);
        g_T[(size_t)(bq * 16 + bb) * KK * JJ + k * JJ + j] = acc;
    }
}

// ===================== k2: streaming GEMM2 -> exp -> GEMM1 =====================
#define K2_XS 0          // 64*128 = 8192 f, XOR-swizzled
#define K2_TM 8192       // 4096 f
#define K2_C2 12288      // 64*68 = 4352 f
#define K2_FLOATS 16640
#define K2_SMEM (K2_FLOATS * 4)

__global__ __launch_bounds__(256, 3)
void k2_stream(const float* __restrict__ X, int trans)
{
    extern __shared__ float sm[];
    float* xs = sm + K2_XS;
    float* Tm = sm + K2_TM;
    float* c2 = sm + K2_C2;

    const int b = blockIdx.y, split = blockIdx.x;
    const int t = threadIdx.x, lane = t & 31, w = t >> 5;
    const int kg = w & 3, ih = w >> 2;          // group = warps {4ih..4ih+3}
    const int gt = t & 127;
    const int barid = 1 + ih;
    const int iL = ih * 32 + lane;

    const float* __restrict__ xg = X + (size_t)b * (II * JJ);
    float* __restrict__ blg = g_bl + (size_t)b * (KK * II);

    {
        const float4* Tg = (const float4*)(g_T + (size_t)b * KK * JJ);
        #pragma unroll
        for (int ee = 0; ee < 4; ++ee)
            ((float4*)Tm)[t + ee * 256] = Tg[t + ee * 256];
    }
    u64 a1[8][2];
    #pragma unroll
    for (int q = 0; q < 8; ++q) { a1[q][0] = 0; a1[q][1] = 0; }
    __syncthreads();                            // Tm visible to both groups

    for (int ch = 0; ch < NCH; ++ch) {
        const int ibase = split * ILEN + ch * CI;

        // stage own group's 32 rows, XOR-swizzled 16B columns
        #pragma unroll
        for (int ee = 0; ee < 8; ++ee) {
            const int e4 = gt + ee * 128;       // il_loc*32 + j4
            const int il = ih * 32 + (e4 >> 5), j4 = e4 & 31;
            const float4 vv = *(const float4*)(xg + (size_t)(ibase + il) * JJ + j4 * 4);
            *(float4*)(xs + il * 128 + ((j4 ^ (il & 31)) << 2)) = vv;
        }
        float blold[8];
        if (trans) {
            #pragma unroll
            for (int q = 0; q < 8; ++q)
                blold[q] = blg[(size_t)(kg * 8 + q) * II + ibase + iL];
        }
        GBAR(barid);

        // GEMM2: warp = 8 k x 32 i (lane) x 128 j
        u64 a2[8];
        #pragma unroll
        for (int q = 0; q < 8; ++q) a2[q] = 0;
        {
            const float* xr = xs + iL * 128;
            #pragma unroll 4
            for (int jq = 0; jq < 32; ++jq) {
                const ulonglong2 xv = *(const ulonglong2*)(xr + ((jq ^ lane) << 2));
                #pragma unroll
                for (int q = 0; q < 8; ++q) {
                    const ulonglong2 tq = *(const ulonglong2*)(Tm + (kg * 8 + q) * JJ + jq * 4);
                    FMA2(a2[q], tq.x, xv.x, a2[q]);
                    FMA2(a2[q], tq.y, xv.y, a2[q]);
                }
            }
        }
        // bl -> exp (unnormalized), duplicated pairs + partial sum
        {
            float ex[8], ssloc = 0.f;
            #pragma unroll
            for (int q = 0; q < 8; ++q) {
                const float2 f = *(float2*)&a2[q];
                float val = f.x + f.y;
                if (trans) val += blold[q];
                else       blg[(size_t)(kg * 8 + q) * II + ibase + iL] = val;
                ex[q] = __expf(val);            // |bl| small: no max-sub needed
                ssloc += ex[q];
            }
            float* cr = c2 + iL * C2P + kg * 16;
            *(float4*)(cr)      = make_float4(ex[0], ex[0], ex[1], ex[1]);
            *(float4*)(cr + 4)  = make_float4(ex[2], ex[2], ex[3], ex[3]);
            *(float4*)(cr + 8)  = make_float4(ex[4], ex[4], ex[5], ex[5]);
            *(float4*)(cr + 12) = make_float4(ex[6], ex[6], ex[7], ex[7]);
            c2[iL * C2P + 64 + kg] = ssloc;
        }
        GBAR(barid);

        // GEMM1: warp = 8 k x 32 i (own half) x 128 j; inv folded into x
        #pragma unroll 2
        for (int ii = 0; ii < 32; ++ii) {
            const int i = ih * 32 + ii;
            const float4 sp = *(const float4*)(c2 + i * C2P + 64);       // bcast
            const float inv = __frcp_rn(sp.x + sp.y + sp.z + sp.w);
            ulonglong2 xv = *(const ulonglong2*)(xs + i * 128 + ((lane ^ ii) << 2));
            u64 iv; PACK2(iv, inv);
            MUL2(xv.x, xv.x, iv);
            MUL2(xv.y, xv.y, iv);
            const float* cP = c2 + i * C2P + kg * 16;                    // bcast
            const ulonglong2 cd0 = *(const ulonglong2*)(cP);
            const ulonglong2 cd1 = *(const ulonglong2*)(cP + 4);
            const ulonglong2 cd2 = *(const ulonglong2*)(cP + 8);
            const ulonglong2 cd3 = *(const ulonglong2*)(cP + 12);
            FMA2(a1[0][0], cd0.x, xv.x, a1[0][0]); FMA2(a1[0][1], cd0.x, xv.y, a1[0][1]);
            FMA2(a1[1][0], cd0.y, xv.x, a1[1][0]); FMA2(a1[1][1], cd0.y, xv.y, a1[1][1]);
            FMA2(a1[2][0], cd1.x, xv.x, a1[2][0]); FMA2(a1[2][1], cd1.x, xv.y, a1[2][1]);
            FMA2(a1[3][0], cd1.y, xv.x, a1[3][0]); FMA2(a1[3][1], cd1.y, xv.y, a1[3][1]);
            FMA2(a1[4][0], cd2.x, xv.x, a1[4][0]); FMA2(a1[4][1], cd2.x, xv.y, a1[4][1]);
            FMA2(a1[5][0], cd2.y, xv.x, a1[5][0]); FMA2(a1[5][1], cd2.y, xv.y, a1[5][1]);
            FMA2(a1[6][0], cd3.x, xv.x, a1[6][0]); FMA2(a1[6][1], cd3.x, xv.y, a1[6][1]);
            FMA2(a1[7][0], cd3.y, xv.x, a1[7][0]); FMA2(a1[7][1], cd3.y, xv.y, a1[7][1]);
        }
        GBAR(barid);                            // xs/c2 free for next chunk
    }

    float* yp = g_yp + ((size_t)(b * NSPLIT + split) * 2 + ih) * KK * JJ;
    #pragma unroll
    for (int q = 0; q < 8; ++q)
        *(ulonglong2*)(yp + (kg * 8 + q) * JJ + lane * 4) =
            make_ulonglong2(a1[q][0], a1[q][1]);
}

extern "C" void kernel_launch(void* const* d_in, const int* in_sizes, int n_in,
                              void* d_out, int out_size)
{
    (void)in_sizes; (void)n_in; (void)out_size;
    const float* X = (const float*)d_in[0];   // [128, 1152, 128] f32
    const float* W = (const float*)d_in[1];   // [128, 32, 32] f32
    float* out = (float*)d_out;               // [128, 32, 32] f32

    cudaFuncSetAttribute(k2_stream, cudaFuncAttributeMaxDynamicSharedMemorySize, K2_SMEM);

    k_colsum<<<dim3(4, BB), 256>>>(X);
    k1_svt<<<dim3(KK, 8), 256>>>(W, out, 0);
    k2_stream<<<dim3(NSPLIT, BB), 256, K2_SMEM>>>(X, 0);
    k1_svt<<<dim3(KK, 8), 256>>>(W, out, 1);
    k2_stream<<<dim3(NSPLIT, BB), 256, K2_SMEM>>>(X, 1);
    k1_svt<<<dim3(KK, 8), 256>>>(W, out, 2);
}

// round 10
// speedup vs baseline: 1.2569x; 1.2569x over previous
#include <cuda_runtime.h>

// CapsuleLayer dynamic routing, factored + Gram-matrix form.
// X[B=128, I=1152, J=128], W[J=128, K=32, D=32], out V[B=128, K=32, D=32]
//
//  kG  : G[k] = W_k W_k^T (32 blocks) + it0 colsum partials (512 blocks)
//  kY  : per (k, 32 batches): y -> z = G y -> ss = y.z -> T = scale*z
//  k2  : per (split, b): GEMM2 -> softmax -> GEMM1 (two 128-thread groups)
//  kOut: per (k, 32 batches): s = y*W -> v = squash -> out

#define BB 128
#define II 1152
#define JJ 128
#define KK 32
#define DD 32
#define KD 1024
#define NSPLIT 3
#define ILEN 384
#define CI 64
#define NCH 6
#define C2P 36
#define NYP (NSPLIT*2)
#define YMP 36           // ymt pitch (j-major, 32 b + pad)

typedef unsigned long long u64;

#define FMA2(d,a,b,c) asm("fma.rn.f32x2 %0, %1, %2, %3;" : "=l"(d) : "l"(a), "l"(b), "l"(c))
#define ADD2(d,a,b)   asm("add.rn.f32x2 %0, %1, %2;" : "=l"(d) : "l"(a), "l"(b))
#define PACK2(d,s)    asm("mov.b64 %0, {%1, %1};" : "=l"(d) : "r"(__float_as_uint(s)))
#define GBAR(id)      asm volatile("bar.sync %0, 128;" :: "r"(id) : "memory")

__device__ float g_bl[(size_t)BB * KK * II];            // [b][k][i]
__device__ float g_T[(size_t)BB * KK * JJ];             // [b][k][j]
__device__ float g_yp[(size_t)BB * NYP * KK * JJ];      // [b][slot][k][j]
__device__ float g_ycol[(size_t)BB * 4 * JJ];           // [b][p][j]
__device__ float g_G[(size_t)KK * JJ * JJ];             // [k][j'][j]

// ===================== kG: Gram build + it0 colsum =====================
__global__ __launch_bounds__(256)
void kG(const float* __restrict__ W, const float* __restrict__ X)
{
    const int t = threadIdx.x;
    if (blockIdx.x < 32) {
        __shared__ float wsm[JJ * 33];
        const int k = blockIdx.x;
        #pragma unroll
        for (int ee = 0; ee < 16; ++ee) {
            const int idx = t + ee * 256;            // j*32 + d
            wsm[(idx >> 5) * 33 + (idx & 31)] = W[(size_t)(idx >> 5) * KD + k * DD + (idx & 31)];
        }
        __syncthreads();
        const int j = t & 127, half = t >> 7;
        float rj[32];
        #pragma unroll
        for (int d = 0; d < 32; ++d) rj[d] = wsm[j * 33 + d];
        float* Gk = g_G + (size_t)k * (JJ * JJ);
        #pragma unroll 2
        for (int jp = 0; jp < 64; ++jp) {
            const int jpg = half * 64 + jp;
            float acc = 0.f;
            #pragma unroll
            for (int d = 0; d < 32; ++d)
                acc = fmaf(rj[d], wsm[jpg * 33 + d], acc);   // bcast
            Gk[jpg * JJ + j] = acc;                          // coalesced
        }
        return;
    }
    __shared__ ulonglong2 sred[256];
    const int bid = blockIdx.x - 32;
    const int b = bid & 127, p = bid >> 7;
    const int j4 = t & 31, ih = t >> 5;
    const float* xp = X + (size_t)b * (II * JJ) + (size_t)(p * 288 + ih * 36) * JJ + j4 * 4;
    u64 s0 = 0, s1 = 0;
    #pragma unroll 4
    for (int ii = 0; ii < 36; ++ii) {
        ulonglong2 v = *(const ulonglong2*)(xp + (size_t)ii * JJ);
        ADD2(s0, s0, v.x); ADD2(s1, s1, v.y);
    }
    sred[ih * 32 + j4] = make_ulonglong2(s0, s1);
    __syncthreads();
    if (t < 32) {
        u64 a0 = 0, a1 = 0;
        #pragma unroll
        for (int h = 0; h < 8; ++h) {
            ulonglong2 v = sred[h * 32 + t];
            ADD2(a0, a0, v.x); ADD2(a1, a1, v.y);
        }
        ((ulonglong2*)(g_ycol + (size_t)(b * 4 + p) * JJ))[t] = make_ulonglong2(a0, a1);
    }
}

// ===================== kY: y -> z=Gy -> scale -> T  (one k, 32 batches) =====================
#define KY_G   0                    // 16384 f
#define KY_YT  16384                // 128*36 = 4608 f  [j][b]
#define KY_SB  (KY_YT + 4608)       // 128 f ss partials
#define KY_SC  (KY_SB + 128)        // 32 f scales
#define KY_FLOATS (KY_SC + 32)
#define KY_SMEM (KY_FLOATS * 4)

__global__ __launch_bounds__(256)
void kY(int mode)                   // 0: y from colsum ; 1: y from g_yp
{
    extern __shared__ float sm[];
    float* Gs   = sm + KY_G;
    float* ymt  = sm + KY_YT;
    float* ssb  = sm + KY_SB;
    float* scl  = sm + KY_SC;

    const int k = blockIdx.x, b0 = blockIdx.y * 32;
    const int t = threadIdx.x;

    // stage G[k] (64KB, coalesced float4)
    {
        const float4* Gg = (const float4*)(g_G + (size_t)k * (JJ * JJ));
        #pragma unroll
        for (int ee = 0; ee < 16; ++ee)
            ((float4*)Gs)[t + ee * 256] = Gg[t + ee * 256];
    }
    // stage y transposed: ymt[j][b]
    {
        const int bL = t >> 6, jj = (t & 63) * 2;
        #pragma unroll
        for (int pass = 0; pass < 8; ++pass) {
            const int b = pass * 4 + bL;
            float v0, v1;
            if (mode == 0) {
                const float* yc = g_ycol + (size_t)(b0 + b) * 4 * JJ;
                v0 = (yc[jj] + yc[128 + jj] + yc[256 + jj] + yc[384 + jj]) * (1.0f / 32.0f);
                v1 = (yc[jj+1] + yc[129 + jj] + yc[257 + jj] + yc[385 + jj]) * (1.0f / 32.0f);
            } else {
                const float* yp = g_yp + (size_t)(b0 + b) * NYP * KK * JJ + (size_t)k * JJ + jj;
                v0 = 0.f; v1 = 0.f;
                #pragma unroll
                for (int s = 0; s < NYP; ++s) {
                    const float2 u = *(const float2*)(yp + (size_t)s * KK * JJ);
                    v0 += u.x; v1 += u.y;
                }
            }
            ymt[jj * YMP + b] = v0;
            ymt[(jj + 1) * YMP + b] = v1;
        }
    }
    __syncthreads();

    // z[b][j] for 16 b per thread: j = t&127, bh = t>>7
    const int j = t & 127, bh = t >> 7;
    float z[16];
    #pragma unroll
    for (int r = 0; r < 16; ++r) z[r] = 0.f;
    #pragma unroll 4
    for (int jp = 0; jp < JJ; ++jp) {
        const float g = Gs[jp * JJ + j];                    // conflict-free
        const float4 y0 = *(const float4*)(ymt + jp * YMP + bh * 16);      // bcast
        const float4 y1 = *(const float4*)(ymt + jp * YMP + bh * 16 + 4);
        const float4 y2 = *(const float4*)(ymt + jp * YMP + bh * 16 + 8);
        const float4 y3 = *(const float4*)(ymt + jp * YMP + bh * 16 + 12);
        z[0]  = fmaf(y0.x, g, z[0]);  z[1]  = fmaf(y0.y, g, z[1]);
        z[2]  = fmaf(y0.z, g, z[2]);  z[3]  = fmaf(y0.w, g, z[3]);
        z[4]  = fmaf(y1.x, g, z[4]);  z[5]  = fmaf(y1.y, g, z[5]);
        z[6]  = fmaf(y1.z, g, z[6]);  z[7]  = fmaf(y1.w, g, z[7]);
        z[8]  = fmaf(y2.x, g, z[8]);  z[9]  = fmaf(y2.y, g, z[9]);
        z[10] = fmaf(y2.z, g, z[10]); z[11] = fmaf(y2.w, g, z[11]);
        z[12] = fmaf(y3.x, g, z[12]); z[13] = fmaf(y3.y, g, z[13]);
        z[14] = fmaf(y3.z, g, z[14]); z[15] = fmaf(y3.w, g, z[15]);
    }

    // ss[b] = sum_j y[b][j] z[b][j]  (warp covers 32 consecutive j)
    {
        float ssp[16];
        #pragma unroll
        for (int r = 0; r < 16; ++r)
            ssp[r] = ymt[j * YMP + bh * 16 + r] * z[r];
        #pragma unroll
        for (int off = 16; off > 0; off >>= 1) {
            #pragma unroll
            for (int r = 0; r < 16; ++r)
                ssp[r] += __shfl_xor_sync(0xffffffffu, ssp[r], off);
        }
        const int w = t >> 5, jw = w & 3;                   // bh = w>>2
        if ((t & 31) == 0) {
            #pragma unroll
            for (int r = 0; r < 16; ++r)
                ssb[jw * 32 + bh * 16 + r] = ssp[r];
        }
    }
    __syncthreads();
    if (t < 32) {
        const float ss = ssb[t] + ssb[32 + t] + ssb[64 + t] + ssb[96 + t];
        scl[t] = ss / (1.0f + ss) * rsqrtf(ss + 1e-7f);
    }
    __syncthreads();

    // T[b][k][j] = scale_b * z
    #pragma unroll
    for (int r = 0; r < 16; ++r) {
        const int b = bh * 16 + r;
        g_T[(size_t)(b0 + b) * KK * JJ + (size_t)k * JJ + j] = z[r] * scl[b];
    }
}

// ===================== kOut: s = y*W -> squash -> out =====================
#define KO_W  0                     // 128*33 = 4224
#define KO_Y  4224                  // 32*128 = 4096  [b][j]
#define KO_FLOATS (KO_Y + 4096)
#define KO_SMEM (KO_FLOATS * 4)

__global__ __launch_bounds__(256)
void kOut(const float* __restrict__ W, float* __restrict__ out)
{
    extern __shared__ float sm[];
    float* wsm = sm + KO_W;
    float* ymb = sm + KO_Y;

    const int k = blockIdx.x, b0 = blockIdx.y * 32;
    const int t = threadIdx.x;

    #pragma unroll
    for (int ee = 0; ee < 16; ++ee) {
        const int idx = t + ee * 256;
        wsm[(idx >> 5) * 33 + (idx & 31)] = W[(size_t)(idx >> 5) * KD + k * DD + (idx & 31)];
    }
    {
        const int bL = t >> 6, jj = (t & 63) * 2;
        #pragma unroll
        for (int pass = 0; pass < 8; ++pass) {
            const int b = pass * 4 + bL;
            const float* yp = g_yp + (size_t)(b0 + b) * NYP * KK * JJ + (size_t)k * JJ + jj;
            float v0 = 0.f, v1 = 0.f;
            #pragma unroll
            for (int s = 0; s < NYP; ++s) {
                const float2 u = *(const float2*)(yp + (size_t)s * KK * JJ);
                v0 += u.x; v1 += u.y;
            }
            ymb[b * JJ + jj] = v0;
            ymb[b * JJ + jj + 1] = v1;
        }
    }
    __syncthreads();

    const int b = t >> 3, d0 = t & 7;
    float s4[4] = {0.f, 0.f, 0.f, 0.f};
    #pragma unroll 4
    for (int j = 0; j < JJ; ++j) {
        const float yv = ymb[b * JJ + j];                   // 8-lane bcast
        #pragma unroll
        for (int q = 0; q < 4; ++q)
            s4[q] = fmaf(yv, wsm[j * 33 + d0 + 8 * q], s4[q]);
    }
    float ssp = s4[0]*s4[0] + s4[1]*s4[1] + s4[2]*s4[2] + s4[3]*s4[3];
    ssp += __shfl_xor_sync(0xffffffffu, ssp, 1, 8);
    ssp += __shfl_xor_sync(0xffffffffu, ssp, 2, 8);
    ssp += __shfl_xor_sync(0xffffffffu, ssp, 4, 8);
    const float scale = ssp / (1.0f + ssp) * rsqrtf(ssp + 1e-7f);
    #pragma unroll
    for (int q = 0; q < 4; ++q)
        out[(size_t)(b0 + b) * KK * DD + k * DD + d0 + 8 * q] = s4[q] * scale;
}

// ===================== k2: streaming GEMM2 -> softmax -> GEMM1 (Round-8 v3) =====================
#define K2_XS 0          // 64*128 = 8192 f, XOR-swizzled
#define K2_TM 8192       // 4096 f
#define K2_C2 12288      // 64*36: c at [0,32), partial sums at [32,36)
#define K2_FLOATS 14592
#define K2_SMEM (K2_FLOATS * 4)

__global__ __launch_bounds__(256, 3)
void k2_stream(const float* __restrict__ X, int trans)
{
    extern __shared__ float sm[];
    float* xs = sm + K2_XS;
    float* Tm = sm + K2_TM;
    float* c2 = sm + K2_C2;

    const int b = blockIdx.y, split = blockIdx.x;
    const int t = threadIdx.x, lane = t & 31, w = t >> 5;
    const int kg = w & 3, ih = w >> 2;
    const int gt = t & 127;
    const int barid = 1 + ih;
    const int iL = ih * 32 + lane;

    const float* __restrict__ xg = X + (size_t)b * (II * JJ);
    float* __restrict__ blg = g_bl + (size_t)b * (KK * II);

    {
        const float4* Tg = (const float4*)(g_T + (size_t)b * KK * JJ);
        #pragma unroll
        for (int ee = 0; ee < 4; ++ee)
            ((float4*)Tm)[t + ee * 256] = Tg[t + ee * 256];
    }
    u64 a1[8][2];
    #pragma unroll
    for (int q = 0; q < 8; ++q) { a1[q][0] = 0; a1[q][1] = 0; }
    __syncthreads();

    for (int ch = 0; ch < NCH; ++ch) {
        const int ibase = split * ILEN + ch * CI;

        #pragma unroll
        for (int ee = 0; ee < 8; ++ee) {
            const int e4 = gt + ee * 128;
            const int il = ih * 32 + (e4 >> 5), j4 = e4 & 31;
            const float4 vv = *(const float4*)(xg + (size_t)(ibase + il) * JJ + j4 * 4);
            *(float4*)(xs + il * 128 + ((j4 ^ (il & 31)) << 2)) = vv;
        }
        float blold[8];
        if (trans) {
            #pragma unroll
            for (int q = 0; q < 8; ++q)
                blold[q] = blg[(size_t)(kg * 8 + q) * II + ibase + iL];
        }
        GBAR(barid);

        u64 a2[8];
        #pragma unroll
        for (int q = 0; q < 8; ++q) a2[q] = 0;
        {
            const float* xr = xs + iL * 128;
            #pragma unroll 4
            for (int jq = 0; jq < 32; ++jq) {
                const ulonglong2 xv = *(const ulonglong2*)(xr + ((jq ^ lane) << 2));
                #pragma unroll
                for (int q = 0; q < 8; ++q) {
                    const ulonglong2 tq = *(const ulonglong2*)(Tm + (kg * 8 + q) * JJ + jq * 4);
                    FMA2(a2[q], tq.x, xv.x, a2[q]);
                    FMA2(a2[q], tq.y, xv.y, a2[q]);
                }
            }
        }
        float ex[8], ssloc = 0.f;
        #pragma unroll
        for (int q = 0; q < 8; ++q) {
            const float2 f = *(float2*)&a2[q];
            float val = f.x + f.y;
            if (trans) val += blold[q];
            else       blg[(size_t)(kg * 8 + q) * II + ibase + iL] = val;
            ex[q] = __expf(val);
            ssloc += ex[q];
        }
        c2[iL * C2P + 32 + kg] = ssloc;
        GBAR(barid);

        {
            const float4 sp = *(const float4*)(c2 + iL * C2P + 32);
            const float inv = 1.0f / (sp.x + sp.y + sp.z + sp.w);
            *(float4*)(c2 + iL * C2P + kg * 8) =
                make_float4(ex[0] * inv, ex[1] * inv, ex[2] * inv, ex[3] * inv);
            *(float4*)(c2 + iL * C2P + kg * 8 + 4) =
                make_float4(ex[4] * inv, ex[5] * inv, ex[6] * inv, ex[7] * inv);
        }
        GBAR(barid);

        #pragma unroll 2
        for (int ii = 0; ii < 32; ++ii) {
            const int i = ih * 32 + ii;
            const ulonglong2 xv = *(const ulonglong2*)(xs + i * 128 + ((lane ^ ii) << 2));
            const float4 c0 = *(const float4*)(c2 + i * C2P + kg * 8);
            const float4 c1 = *(const float4*)(c2 + i * C2P + kg * 8 + 4);
            u64 cc;
            PACK2(cc, c0.x); FMA2(a1[0][0], cc, xv.x, a1[0][0]); FMA2(a1[0][1], cc, xv.y, a1[0][1]);
            PACK2(cc, c0.y); FMA2(a1[1][0], cc, xv.x, a1[1][0]); FMA2(a1[1][1], cc, xv.y, a1[1][1]);
            PACK2(cc, c0.z); FMA2(a1[2][0], cc, xv.x, a1[2][0]); FMA2(a1[2][1], cc, xv.y, a1[2][1]);
            PACK2(cc, c0.w); FMA2(a1[3][0], cc, xv.x, a1[3][0]); FMA2(a1[3][1], cc, xv.y, a1[3][1]);
            PACK2(cc, c1.x); FMA2(a1[4][0], cc, xv.x, a1[4][0]); FMA2(a1[4][1], cc, xv.y, a1[4][1]);
            PACK2(cc, c1.y); FMA2(a1[5][0], cc, xv.x, a1[5][0]); FMA2(a1[5][1], cc, xv.y, a1[5][1]);
            PACK2(cc, c1.z); FMA2(a1[6][0], cc, xv.x, a1[6][0]); FMA2(a1[6][1], cc, xv.y, a1[6][1]);
            PACK2(cc, c1.w); FMA2(a1[7][0], cc, xv.x, a1[7][0]); FMA2(a1[7][1], cc, xv.y, a1[7][1]);
        }
        GBAR(barid);
    }

    float* yp = g_yp + ((size_t)(b * NSPLIT + split) * 2 + ih) * KK * JJ;
    #pragma unroll
    for (int q = 0; q < 8; ++q)
        *(ulonglong2*)(yp + (kg * 8 + q) * JJ + lane * 4) =
            make_ulonglong2(a1[q][0], a1[q][1]);
}

extern "C" void kernel_launch(void* const* d_in, const int* in_sizes, int n_in,
                              void* d_out, int out_size)
{
    (void)in_sizes; (void)n_in; (void)out_size;
    const float* X = (const float*)d_in[0];   // [128, 1152, 128] f32
    const float* W = (const float*)d_in[1];   // [128, 32, 32] f32
    float* out = (float*)d_out;               // [128, 32, 32] f32

    cudaFuncSetAttribute(kY, cudaFuncAttributeMaxDynamicSharedMemorySize, KY_SMEM);
    cudaFuncSetAttribute(kOut, cudaFuncAttributeMaxDynamicSharedMemorySize, KO_SMEM);
    cudaFuncSetAttribute(k2_stream, cudaFuncAttributeMaxDynamicSharedMemorySize, K2_SMEM);

    kG<<<32 + 512, 256>>>(W, X);
    kY<<<dim3(KK, 4), 256, KY_SMEM>>>(0);
    k2_stream<<<dim3(NSPLIT, BB), 256, K2_SMEM>>>(X, 0);
    kY<<<dim3(KK, 4), 256, KY_SMEM>>>(1);
    k2_stream<<<dim3(NSPLIT, BB), 256, K2_SMEM>>>(X, 1);
    kOut<<<dim3(KK, 4), 256, KO_SMEM>>>(W, out);
}

// round 11
// speedup vs baseline: 1.3034x; 1.0370x over previous
#include <cuda_runtime.h>

// CapsuleLayer dynamic routing, factored + Gram form, v6.
// X[B=128, I=1152, J=128], W[J=128, K=32, D=32], out V[B=128, K=32, D=32]
//  kG  : G[k] = W_k W_k^T + it0 colsum partials
//  kY  : per (k, 16 batches): y -> z = G y (G from L2) -> ss -> T = scale*z
//  k2  : per (split, b): cp.async double-buffered chunks, two 128-thread groups,
//        GEMM2 -> exp -> norm -> GEMM1, 3 named barriers per chunk
//  kOut: s = y*W -> squash -> out

#define BB 128
#define II 1152
#define JJ 128
#define KK 32
#define DD 32
#define KD 1024
#define NSPLIT 2
#define ILEN 576
#define CI 64
#define NCH 9
#define C2P 36
#define NYP (NSPLIT*2)
#define YMP 20

typedef unsigned long long u64;

#define FMA2(d,a,b,c) asm("fma.rn.f32x2 %0, %1, %2, %3;" : "=l"(d) : "l"(a), "l"(b), "l"(c))
#define ADD2(d,a,b)   asm("add.rn.f32x2 %0, %1, %2;" : "=l"(d) : "l"(a), "l"(b))
#define PACK2(d,s)    asm("mov.b64 %0, {%1, %1};" : "=l"(d) : "r"(__float_as_uint(s)))
#define GBAR(id)      asm volatile("bar.sync %0, 128;" :: "r"(id) : "memory")
#define CP_COMMIT()   asm volatile("cp.async.commit_group;\n" ::: "memory")
#define CP_WAIT0()    asm volatile("cp.async.wait_group 0;\n" ::: "memory")

__device__ float g_bl[(size_t)BB * KK * II];            // [b][k][i]
__device__ float g_T[(size_t)BB * KK * JJ];             // [b][k][j]
__device__ float g_yp[(size_t)BB * NYP * KK * JJ];      // [b][slot][k][j]
__device__ float g_ycol[(size_t)BB * 4 * JJ];           // [b][p][j]
__device__ float g_G[(size_t)KK * JJ * JJ];             // [k][j'][j]

// ===================== kG: Gram build + it0 colsum =====================
__global__ __launch_bounds__(256)
void kG(const float* __restrict__ W, const float* __restrict__ X)
{
    const int t = threadIdx.x;
    if (blockIdx.x < 32) {
        __shared__ float wsm[JJ * 33];
        const int k = blockIdx.x;
        #pragma unroll
        for (int ee = 0; ee < 16; ++ee) {
            const int idx = t + ee * 256;            // j*32 + d
            wsm[(idx >> 5) * 33 + (idx & 31)] = W[(size_t)(idx >> 5) * KD + k * DD + (idx & 31)];
        }
        __syncthreads();
        const int j = t & 127, half = t >> 7;
        float rj[32];
        #pragma unroll
        for (int d = 0; d < 32; ++d) rj[d] = wsm[j * 33 + d];
        float* Gk = g_G + (size_t)k * (JJ * JJ);
        #pragma unroll 2
        for (int jp = 0; jp < 64; ++jp) {
            const int jpg = half * 64 + jp;
            float acc = 0.f;
            #pragma unroll
            for (int d = 0; d < 32; ++d)
                acc = fmaf(rj[d], wsm[jpg * 33 + d], acc);
            Gk[jpg * JJ + j] = acc;
        }
        return;
    }
    __shared__ ulonglong2 sred[256];
    const int bid = blockIdx.x - 32;
    const int b = bid & 127, p = bid >> 7;
    const int j4 = t & 31, ih = t >> 5;
    const float* xp = X + (size_t)b * (II * JJ) + (size_t)(p * 288 + ih * 36) * JJ + j4 * 4;
    u64 s0 = 0, s1 = 0;
    #pragma unroll 4
    for (int ii = 0; ii < 36; ++ii) {
        ulonglong2 v = *(const ulonglong2*)(xp + (size_t)ii * JJ);
        ADD2(s0, s0, v.x); ADD2(s1, s1, v.y);
    }
    sred[ih * 32 + j4] = make_ulonglong2(s0, s1);
    __syncthreads();
    if (t < 32) {
        u64 a0 = 0, a1 = 0;
        #pragma unroll
        for (int h = 0; h < 8; ++h) {
            ulonglong2 v = sred[h * 32 + t];
            ADD2(a0, a0, v.x); ADD2(a1, a1, v.y);
        }
        ((ulonglong2*)(g_ycol + (size_t)(b * 4 + p) * JJ))[t] = make_ulonglong2(a0, a1);
    }
}

// ===================== kY: y -> z = G y -> scale -> T  (one k, 16 batches) =====================
__global__ __launch_bounds__(256)
void kY(int mode)                   // 0: y from colsum ; 1: y from g_yp
{
    __shared__ float ymt[JJ * YMP];     // [j][b], pitch 20
    __shared__ float ssb[64];
    __shared__ float scl[16];

    const int k = blockIdx.x, b0 = blockIdx.y * 16;
    const int t = threadIdx.x;

    // stage y transposed: ymt[j][b]
    {
        const int bL = t >> 6, jj = (t & 63) * 2;
        #pragma unroll
        for (int pass = 0; pass < 4; ++pass) {
            const int b = pass * 4 + bL;
            float v0, v1;
            if (mode == 0) {
                const float* yc = g_ycol + (size_t)(b0 + b) * 4 * JJ;
                v0 = (yc[jj]   + yc[128 + jj] + yc[256 + jj] + yc[384 + jj]) * (1.0f / 32.0f);
                v1 = (yc[jj+1] + yc[129 + jj] + yc[257 + jj] + yc[385 + jj]) * (1.0f / 32.0f);
            } else {
                const float* yp = g_yp + (size_t)(b0 + b) * NYP * KK * JJ + (size_t)k * JJ + jj;
                v0 = 0.f; v1 = 0.f;
                #pragma unroll
                for (int s = 0; s < NYP; ++s) {
                    const float2 u = *(const float2*)(yp + (size_t)s * KK * JJ);
                    v0 += u.x; v1 += u.y;
                }
            }
            ymt[jj * YMP + b] = v0;
            ymt[(jj + 1) * YMP + b] = v1;
        }
    }
    __syncthreads();

    // z[b][j], 8 b per thread; G streamed from L2 (coalesced)
    const int j = t & 127, bh = t >> 7;
    const float* Gk = g_G + (size_t)k * (JJ * JJ) + j;
    float z[8];
    #pragma unroll
    for (int r = 0; r < 8; ++r) z[r] = 0.f;
    #pragma unroll 4
    for (int jp = 0; jp < JJ; ++jp) {
        const float g = Gk[jp * JJ];                        // coalesced LDG
        const float4 y0 = *(const float4*)(ymt + jp * YMP + bh * 8);       // bcast
        const float4 y1 = *(const float4*)(ymt + jp * YMP + bh * 8 + 4);
        z[0] = fmaf(y0.x, g, z[0]); z[1] = fmaf(y0.y, g, z[1]);
        z[2] = fmaf(y0.z, g, z[2]); z[3] = fmaf(y0.w, g, z[3]);
        z[4] = fmaf(y1.x, g, z[4]); z[5] = fmaf(y1.y, g, z[5]);
        z[6] = fmaf(y1.z, g, z[6]); z[7] = fmaf(y1.w, g, z[7]);
    }

    // ss[b] = sum_j y z
    {
        float ssp[8];
        #pragma unroll
        for (int r = 0; r < 8; ++r)
            ssp[r] = ymt[j * YMP + bh * 8 + r] * z[r];
        #pragma unroll
        for (int off = 16; off > 0; off >>= 1) {
            #pragma unroll
            for (int r = 0; r < 8; ++r)
                ssp[r] += __shfl_xor_sync(0xffffffffu, ssp[r], off);
        }
        const int w = t >> 5;
        if ((t & 31) == 0) {
            #pragma unroll
            for (int r = 0; r < 8; ++r)
                ssb[(w & 3) * 16 + bh * 8 + r] = ssp[r];
        }
    }
    __syncthreads();
    if (t < 16) {
        const float ss = ssb[t] + ssb[16 + t] + ssb[32 + t] + ssb[48 + t];
        scl[t] = ss / (1.0f + ss) * rsqrtf(ss + 1e-7f);
    }
    __syncthreads();

    #pragma unroll
    for (int r = 0; r < 8; ++r) {
        const int b = bh * 8 + r;
        g_T[(size_t)(b0 + b) * KK * JJ + (size_t)k * JJ + j] = z[r] * scl[b];
    }
}

// ===================== kOut: s = y*W -> squash -> out =====================
#define KO_W  0                     // 128*33 = 4224
#define KO_Y  4224                  // 32*128 = 4096
#define KO_FLOATS (KO_Y + 4096)
#define KO_SMEM (KO_FLOATS * 4)

__global__ __launch_bounds__(256)
void kOut(const float* __restrict__ W, float* __restrict__ out)
{
    extern __shared__ float sm[];
    float* wsm = sm + KO_W;
    float* ymb = sm + KO_Y;

    const int k = blockIdx.x, b0 = blockIdx.y * 32;
    const int t = threadIdx.x;

    #pragma unroll
    for (int ee = 0; ee < 16; ++ee) {
        const int idx = t + ee * 256;
        wsm[(idx >> 5) * 33 + (idx & 31)] = W[(size_t)(idx >> 5) * KD + k * DD + (idx & 31)];
    }
    {
        const int bL = t >> 6, jj = (t & 63) * 2;
        #pragma unroll
        for (int pass = 0; pass < 8; ++pass) {
            const int b = pass * 4 + bL;
            const float* yp = g_yp + (size_t)(b0 + b) * NYP * KK * JJ + (size_t)k * JJ + jj;
            float v0 = 0.f, v1 = 0.f;
            #pragma unroll
            for (int s = 0; s < NYP; ++s) {
                const float2 u = *(const float2*)(yp + (size_t)s * KK * JJ);
                v0 += u.x; v1 += u.y;
            }
            ymb[b * JJ + jj] = v0;
            ymb[b * JJ + jj + 1] = v1;
        }
    }
    __syncthreads();

    const int b = t >> 3, d0 = t & 7;
    float s4[4] = {0.f, 0.f, 0.f, 0.f};
    #pragma unroll 4
    for (int j = 0; j < JJ; ++j) {
        const float yv = ymb[b * JJ + j];
        #pragma unroll
        for (int q = 0; q < 4; ++q)
            s4[q] = fmaf(yv, wsm[j * 33 + d0 + 8 * q], s4[q]);
    }
    float ssp = s4[0]*s4[0] + s4[1]*s4[1] + s4[2]*s4[2] + s4[3]*s4[3];
    ssp += __shfl_xor_sync(0xffffffffu, ssp, 1, 8);
    ssp += __shfl_xor_sync(0xffffffffu, ssp, 2, 8);
    ssp += __shfl_xor_sync(0xffffffffu, ssp, 4, 8);
    const float scale = ssp / (1.0f + ssp) * rsqrtf(ssp + 1e-7f);
    #pragma unroll
    for (int q = 0; q < 4; ++q)
        out[(size_t)(b0 + b) * KK * DD + k * DD + d0 + 8 * q] = s4[q] * scale;
}

// ===================== k2: cp.async pipelined GEMM2 -> softmax -> GEMM1 =====================
#define K2_XS0 0         // buf0: 8192 f (XOR swizzle)
#define K2_XS1 8192      // buf1: 8192 f
#define K2_TM  16384     // 4096 f
#define K2_C2  20480     // 64*36 = 2304 f
#define K2_FLOATS 22784
#define K2_SMEM (K2_FLOATS * 4)

__global__ __launch_bounds__(256, 2)
void k2_stream(const float* __restrict__ X, int trans)
{
    extern __shared__ float sm[];
    float* Tm = sm + K2_TM;
    float* c2 = sm + K2_C2;

    const int b = blockIdx.y, split = blockIdx.x;
    const int t = threadIdx.x, lane = t & 31, w = t >> 5;
    const int kg = w & 3, ih = w >> 2;
    const int gt = t & 127;
    const int barid = 1 + ih;
    const int iL = ih * 32 + lane;

    const float* __restrict__ xg = X + (size_t)b * (II * JJ);
    float* __restrict__ blg = g_bl + (size_t)b * (KK * II);
    const unsigned smbase = (unsigned)__cvta_generic_to_shared(sm);

    {
        const float4* Tg = (const float4*)(g_T + (size_t)b * KK * JJ);
        #pragma unroll
        for (int ee = 0; ee < 4; ++ee)
            ((float4*)Tm)[t + ee * 256] = Tg[t + ee * 256];
    }
    u64 a1[8][2];
    #pragma unroll
    for (int q = 0; q < 8; ++q) { a1[q][0] = 0; a1[q][1] = 0; }

    // preload chunk 0 into buf0 (own group's rows)
    {
        const int ibase = split * ILEN;
        #pragma unroll
        for (int ee = 0; ee < 8; ++ee) {
            const int e4 = gt + ee * 128;
            const int il = ih * 32 + (e4 >> 5), j4 = e4 & 31;
            const unsigned dst = smbase + (unsigned)(il * 128 + ((j4 ^ (il & 31)) << 2)) * 4u;
            asm volatile("cp.async.cg.shared.global [%0], [%1], 16;\n"
                         :: "r"(dst), "l"(xg + (size_t)(ibase + il) * JJ + j4 * 4));
        }
        CP_COMMIT();
    }
    __syncthreads();                            // Tm visible; groups aligned

    for (int ch = 0; ch < NCH; ++ch) {
        const int ibase = split * ILEN + ch * CI;
        const float* xb = sm + ((ch & 1) ? K2_XS1 : K2_XS0);

        CP_WAIT0();
        GBAR(barid);   // chunk data in; prev chunk's GEMM1 done (c2/other-buf free)

        // issue next chunk into the other buffer (overlaps all compute below)
        if (ch + 1 < NCH) {
            const unsigned boff = ((ch & 1) ? K2_XS0 : K2_XS1) * 4u;
            const float* src = xg + (size_t)(ibase + CI) * JJ;
            #pragma unroll
            for (int ee = 0; ee < 8; ++ee) {
                const int e4 = gt + ee * 128;
                const int il = ih * 32 + (e4 >> 5), j4 = e4 & 31;
                const unsigned dst = smbase + boff + (unsigned)(il * 128 + ((j4 ^ (il & 31)) << 2)) * 4u;
                asm volatile("cp.async.cg.shared.global [%0], [%1], 16;\n"
                             :: "r"(dst), "l"(src + (size_t)il * JJ + j4 * 4));
            }
            CP_COMMIT();
        }
        float blold[8];
        if (trans) {
            #pragma unroll
            for (int q = 0; q < 8; ++q)
                blold[q] = blg[(size_t)(kg * 8 + q) * II + ibase + iL];
        }

        // GEMM2: warp = 8 k x 32 i (lane) x 128 j
        u64 a2[8];
        #pragma unroll
        for (int q = 0; q < 8; ++q) a2[q] = 0;
        {
            const float* xr = xb + iL * 128;
            #pragma unroll 4
            for (int jq = 0; jq < 32; ++jq) {
                const ulonglong2 xv = *(const ulonglong2*)(xr + ((jq ^ lane) << 2));
                #pragma unroll
                for (int q = 0; q < 8; ++q) {
                    const ulonglong2 tq = *(const ulonglong2*)(Tm + (kg * 8 + q) * JJ + jq * 4);
                    FMA2(a2[q], tq.x, xv.x, a2[q]);
                    FMA2(a2[q], tq.y, xv.y, a2[q]);
                }
            }
        }
        float ex[8], ssloc = 0.f;
        #pragma unroll
        for (int q = 0; q < 8; ++q) {
            const float2 f = *(float2*)&a2[q];
            float val = f.x + f.y;
            if (trans) val += blold[q];
            else       blg[(size_t)(kg * 8 + q) * II + ibase + iL] = val;
            ex[q] = __expf(val);                // |bl| small: max-sub not needed
            ssloc += ex[q];
        }
        c2[iL * C2P + 32 + kg] = ssloc;
        GBAR(barid);

        {
            const float4 sp = *(const float4*)(c2 + iL * C2P + 32);
            const float inv = 1.0f / (sp.x + sp.y + sp.z + sp.w);
            *(float4*)(c2 + iL * C2P + kg * 8) =
                make_float4(ex[0] * inv, ex[1] * inv, ex[2] * inv, ex[3] * inv);
            *(float4*)(c2 + iL * C2P + kg * 8 + 4) =
                make_float4(ex[4] * inv, ex[5] * inv, ex[6] * inv, ex[7] * inv);
        }
        GBAR(barid);

        // GEMM1: warp = 8 k x 32 i (own half) x 128 j
        #pragma unroll 2
        for (int ii = 0; ii < 32; ++ii) {
            const int i = ih * 32 + ii;
            const ulonglong2 xv = *(const ulonglong2*)(xb + i * 128 + ((lane ^ ii) << 2));
            const float4 c0 = *(const float4*)(c2 + i * C2P + kg * 8);
            const float4 c1 = *(const float4*)(c2 + i * C2P + kg * 8 + 4);
            u64 cc;
            PACK2(cc, c0.x); FMA2(a1[0][0], cc, xv.x, a1[0][0]); FMA2(a1[0][1], cc, xv.y, a1[0][1]);
            PACK2(cc, c0.y); FMA2(a1[1][0], cc, xv.x, a1[1][0]); FMA2(a1[1][1], cc, xv.y, a1[1][1]);
            PACK2(cc, c0.z); FMA2(a1[2][0], cc, xv.x, a1[2][0]); FMA2(a1[2][1], cc, xv.y, a1[2][1]);
            PACK2(cc, c0.w); FMA2(a1[3][0], cc, xv.x, a1[3][0]); FMA2(a1[3][1], cc, xv.y, a1[3][1]);
            PACK2(cc, c1.x); FMA2(a1[4][0], cc, xv.x, a1[4][0]); FMA2(a1[4][1], cc, xv.y, a1[4][1]);
            PACK2(cc, c1.y); FMA2(a1[5][0], cc, xv.x, a1[5][0]); FMA2(a1[5][1], cc, xv.y, a1[5][1]);
            PACK2(cc, c1.z); FMA2(a1[6][0], cc, xv.x, a1[6][0]); FMA2(a1[6][1], cc, xv.y, a1[6][1]);
            PACK2(cc, c1.w); FMA2(a1[7][0], cc, xv.x, a1[7][0]); FMA2(a1[7][1], cc, xv.y, a1[7][1]);
        }
        // loop-top GBAR orders these reads vs. c2/buffer reuse
    }

    float* yp = g_yp + ((size_t)(b * NSPLIT + split) * 2 + ih) * KK * JJ;
    #pragma unroll
    for (int q = 0; q < 8; ++q)
        *(ulonglong2*)(yp + (kg * 8 + q) * JJ + lane * 4) =
            make_ulonglong2(a1[q][0], a1[q][1]);
}

extern "C" void kernel_launch(void* const* d_in, const int* in_sizes, int n_in,
                              void* d_out, int out_size)
{
    (void)in_sizes; (void)n_in; (void)out_size;
    const float* X = (const float*)d_in[0];   // [128, 1152, 128] f32
    const float* W = (const float*)d_in[1];   // [128, 32, 32] f32
    float* out = (float*)d_out;               // [128, 32, 32] f32

    cudaFuncSetAttribute(kOut, cudaFuncAttributeMaxDynamicSharedMemorySize, KO_SMEM);
    cudaFuncSetAttribute(k2_stream, cudaFuncAttributeMaxDynamicSharedMemorySize, K2_SMEM);

    kG<<<32 + 512, 256>>>(W, X);
    kY<<<dim3(KK, 8), 256>>>(0);
    k2_stream<<<dim3(NSPLIT, BB), 256, K2_SMEM>>>(X, 0);
    kY<<<dim3(KK, 8), 256>>>(1);
    k2_stream<<<dim3(NSPLIT, BB), 256, K2_SMEM>>>(X, 1);
    kOut<<<dim3(KK, 4), 256, KO_SMEM>>>(W, out);
}

// round 12
// speedup vs baseline: 1.3519x; 1.0373x over previous
#include <cuda_runtime.h>

// CapsuleLayer dynamic routing, factored + Gram form, v7.
// X[B=128, I=1152, J=128], W[J=128, K=32, D=32], out V[B=128, K=32, D=32]
//  kG  : G[k] = W_k W_k^T + it0 colsum partials
//  kY  : per (k, 16 batches): y -> z = G y (G from L2, 8-deep reg prefetch) -> T
//  k2  : per (split, b): cp.async double-buffered chunks, two 128-thread groups
//  kOut: s = y*W -> squash -> out

#define BB 128
#define II 1152
#define JJ 128
#define KK 32
#define DD 32
#define KD 1024
#define NSPLIT 2
#define ILEN 576
#define CI 64
#define NCH 9
#define C2P 36
#define NYP (NSPLIT*2)
#define YMP 20

typedef unsigned long long u64;

#define FMA2(d,a,b,c) asm("fma.rn.f32x2 %0, %1, %2, %3;" : "=l"(d) : "l"(a), "l"(b), "l"(c))
#define ADD2(d,a,b)   asm("add.rn.f32x2 %0, %1, %2;" : "=l"(d) : "l"(a), "l"(b))
#define PACK2(d,s)    asm("mov.b64 %0, {%1, %1};" : "=l"(d) : "r"(__float_as_uint(s)))
#define GBAR(id)      asm volatile("bar.sync %0, 128;" :: "r"(id) : "memory")
#define CP_COMMIT()   asm volatile("cp.async.commit_group;\n" ::: "memory")
#define CP_WAIT0()    asm volatile("cp.async.wait_group 0;\n" ::: "memory")

__device__ float g_bl[(size_t)BB * KK * II];            // [b][k][i]
__device__ float g_T[(size_t)BB * KK * JJ];             // [b][k][j]
__device__ float g_yp[(size_t)BB * NYP * KK * JJ];      // [b][slot][k][j]
__device__ float g_ycol[(size_t)BB * 4 * JJ];           // [b][p][j]
__device__ float g_G[(size_t)KK * JJ * JJ];             // [k][j'][j]

// ===================== kG: Gram build + it0 colsum =====================
__global__ __launch_bounds__(256)
void kG(const float* __restrict__ W, const float* __restrict__ X)
{
    const int t = threadIdx.x;
    if (blockIdx.x < 32) {
        __shared__ float wsm[JJ * 33];
        const int k = blockIdx.x;
        #pragma unroll
        for (int ee = 0; ee < 16; ++ee) {
            const int idx = t + ee * 256;            // j*32 + d
            wsm[(idx >> 5) * 33 + (idx & 31)] = W[(size_t)(idx >> 5) * KD + k * DD + (idx & 31)];
        }
        __syncthreads();
        const int j = t & 127, half = t >> 7;
        float rj[32];
        #pragma unroll
        for (int d = 0; d < 32; ++d) rj[d] = wsm[j * 33 + d];
        float* Gk = g_G + (size_t)k * (JJ * JJ);
        #pragma unroll 2
        for (int jp = 0; jp < 64; ++jp) {
            const int jpg = half * 64 + jp;
            float acc = 0.f;
            #pragma unroll
            for (int d = 0; d < 32; ++d)
                acc = fmaf(rj[d], wsm[jpg * 33 + d], acc);
            Gk[jpg * JJ + j] = acc;
        }
        return;
    }
    __shared__ ulonglong2 sred[256];
    const int bid = blockIdx.x - 32;
    const int b = bid & 127, p = bid >> 7;
    const int j4 = t & 31, ih = t >> 5;
    const float* xp = X + (size_t)b * (II * JJ) + (size_t)(p * 288 + ih * 36) * JJ + j4 * 4;
    u64 s0 = 0, s1 = 0;
    #pragma unroll 4
    for (int ii = 0; ii < 36; ++ii) {
        ulonglong2 v = *(const ulonglong2*)(xp + (size_t)ii * JJ);
        ADD2(s0, s0, v.x); ADD2(s1, s1, v.y);
    }
    sred[ih * 32 + j4] = make_ulonglong2(s0, s1);
    __syncthreads();
    if (t < 32) {
        u64 a0 = 0, a1 = 0;
        #pragma unroll
        for (int h = 0; h < 8; ++h) {
            ulonglong2 v = sred[h * 32 + t];
            ADD2(a0, a0, v.x); ADD2(a1, a1, v.y);
        }
        ((ulonglong2*)(g_ycol + (size_t)(b * 4 + p) * JJ))[t] = make_ulonglong2(a0, a1);
    }
}

// ===================== kY: y -> z = G y -> scale -> T  (one k, 16 batches) =====================
__global__ __launch_bounds__(256)
void kY(int mode)                   // 0: y from colsum ; 1: y from g_yp
{
    __shared__ float ymt[JJ * YMP];     // [j][b], pitch 20
    __shared__ float ssb[64];
    __shared__ float scl[16];

    const int k = blockIdx.x, b0 = blockIdx.y * 16;
    const int t = threadIdx.x;

    // stage y transposed: ymt[j][b]
    {
        const int bL = t >> 6, jj = (t & 63) * 2;
        #pragma unroll
        for (int pass = 0; pass < 4; ++pass) {
            const int b = pass * 4 + bL;
            float v0, v1;
            if (mode == 0) {
                const float* yc = g_ycol + (size_t)(b0 + b) * 4 * JJ;
                v0 = (yc[jj]   + yc[128 + jj] + yc[256 + jj] + yc[384 + jj]) * (1.0f / 32.0f);
                v1 = (yc[jj+1] + yc[129 + jj] + yc[257 + jj] + yc[385 + jj]) * (1.0f / 32.0f);
            } else {
                const float* yp = g_yp + (size_t)(b0 + b) * NYP * KK * JJ + (size_t)k * JJ + jj;
                v0 = 0.f; v1 = 0.f;
                #pragma unroll
                for (int s = 0; s < NYP; ++s) {
                    const float2 u = *(const float2*)(yp + (size_t)s * KK * JJ);
                    v0 += u.x; v1 += u.y;
                }
            }
            ymt[jj * YMP + b] = v0;
            ymt[(jj + 1) * YMP + b] = v1;
        }
    }
    __syncthreads();

    // z[b][j], 8 b per thread; G streamed from L2 with 8-deep register prefetch
    const int j = t & 127, bh = t >> 7;
    const float* Gk = g_G + (size_t)k * (JJ * JJ) + j;
    float z[8];
    #pragma unroll
    for (int r = 0; r < 8; ++r) z[r] = 0.f;

    float gbuf[8];
    #pragma unroll
    for (int u = 0; u < 8; ++u) gbuf[u] = Gk[u * JJ];          // 8 LDGs in flight
    for (int jp = 0; jp < JJ; jp += 8) {
        float gcur[8];
        #pragma unroll
        for (int u = 0; u < 8; ++u) gcur[u] = gbuf[u];
        if (jp + 8 < JJ) {
            #pragma unroll
            for (int u = 0; u < 8; ++u) gbuf[u] = Gk[(jp + 8 + u) * JJ];   // next batch in flight
        }
        #pragma unroll
        for (int u = 0; u < 8; ++u) {
            const float g = gcur[u];
            const float4 y0 = *(const float4*)(ymt + (jp + u) * YMP + bh * 8);       // bcast
            const float4 y1 = *(const float4*)(ymt + (jp + u) * YMP + bh * 8 + 4);
            z[0] = fmaf(y0.x, g, z[0]); z[1] = fmaf(y0.y, g, z[1]);
            z[2] = fmaf(y0.z, g, z[2]); z[3] = fmaf(y0.w, g, z[3]);
            z[4] = fmaf(y1.x, g, z[4]); z[5] = fmaf(y1.y, g, z[5]);
            z[6] = fmaf(y1.z, g, z[6]); z[7] = fmaf(y1.w, g, z[7]);
        }
    }

    // ss[b] = sum_j y z
    {
        float ssp[8];
        #pragma unroll
        for (int r = 0; r < 8; ++r)
            ssp[r] = ymt[j * YMP + bh * 8 + r] * z[r];
        #pragma unroll
        for (int off = 16; off > 0; off >>= 1) {
            #pragma unroll
            for (int r = 0; r < 8; ++r)
                ssp[r] += __shfl_xor_sync(0xffffffffu, ssp[r], off);
        }
        const int w = t >> 5;
        if ((t & 31) == 0) {
            #pragma unroll
            for (int r = 0; r < 8; ++r)
                ssb[(w & 3) * 16 + bh * 8 + r] = ssp[r];
        }
    }
    __syncthreads();
    if (t < 16) {
        const float ss = ssb[t] + ssb[16 + t] + ssb[32 + t] + ssb[48 + t];
        scl[t] = ss / (1.0f + ss) * rsqrtf(ss + 1e-7f);
    }
    __syncthreads();

    #pragma unroll
    for (int r = 0; r < 8; ++r) {
        const int b = bh * 8 + r;
        g_T[(size_t)(b0 + b) * KK * JJ + (size_t)k * JJ + j] = z[r] * scl[b];
    }
}

// ===================== kOut: s = y*W -> squash -> out =====================
#define KO_W  0                     // 128*33 = 4224
#define KO_Y  4224                  // 32*128 = 4096
#define KO_FLOATS (KO_Y + 4096)
#define KO_SMEM (KO_FLOATS * 4)

__global__ __launch_bounds__(256)
void kOut(const float* __restrict__ W, float* __restrict__ out)
{
    extern __shared__ float sm[];
    float* wsm = sm + KO_W;
    float* ymb = sm + KO_Y;

    const int k = blockIdx.x, b0 = blockIdx.y * 32;
    const int t = threadIdx.x;

    #pragma unroll
    for (int ee = 0; ee < 16; ++ee) {
        const int idx = t + ee * 256;
        wsm[(idx >> 5) * 33 + (idx & 31)] = W[(size_t)(idx >> 5) * KD + k * DD + (idx & 31)];
    }
    {
        const int bL = t >> 6, jj = (t & 63) * 2;
        #pragma unroll
        for (int pass = 0; pass < 8; ++pass) {
            const int b = pass * 4 + bL;
            const float* yp = g_yp + (size_t)(b0 + b) * NYP * KK * JJ + (size_t)k * JJ + jj;
            float v0 = 0.f, v1 = 0.f;
            #pragma unroll
            for (int s = 0; s < NYP; ++s) {
                const float2 u = *(const float2*)(yp + (size_t)s * KK * JJ);
                v0 += u.x; v1 += u.y;
            }
            ymb[b * JJ + jj] = v0;
            ymb[b * JJ + jj + 1] = v1;
        }
    }
    __syncthreads();

    const int b = t >> 3, d0 = t & 7;
    float s4[4] = {0.f, 0.f, 0.f, 0.f};
    #pragma unroll 4
    for (int j = 0; j < JJ; ++j) {
        const float yv = ymb[b * JJ + j];
        #pragma unroll
        for (int q = 0; q < 4; ++q)
            s4[q] = fmaf(yv, wsm[j * 33 + d0 + 8 * q], s4[q]);
    }
    float ssp = s4[0]*s4[0] + s4[1]*s4[1] + s4[2]*s4[2] + s4[3]*s4[3];
    ssp += __shfl_xor_sync(0xffffffffu, ssp, 1, 8);
    ssp += __shfl_xor_sync(0xffffffffu, ssp, 2, 8);
    ssp += __shfl_xor_sync(0xffffffffu, ssp, 4, 8);
    const float scale = ssp / (1.0f + ssp) * rsqrtf(ssp + 1e-7f);
    #pragma unroll
    for (int q = 0; q < 4; ++q)
        out[(size_t)(b0 + b) * KK * DD + k * DD + d0 + 8 * q] = s4[q] * scale;
}

// ===================== k2: cp.async pipelined GEMM2 -> softmax -> GEMM1 =====================
#define K2_XS0 0         // buf0: 8192 f (XOR swizzle)
#define K2_XS1 8192      // buf1: 8192 f
#define K2_TM  16384     // 4096 f
#define K2_C2  20480     // 64*36 = 2304 f
#define K2_FLOATS 22784
#define K2_SMEM (K2_FLOATS * 4)

__global__ __launch_bounds__(256, 2)
void k2_stream(const float* __restrict__ X, int trans)
{
    extern __shared__ float sm[];
    float* Tm = sm + K2_TM;
    float* c2 = sm + K2_C2;

    const int b = blockIdx.y, split = blockIdx.x;
    const int t = threadIdx.x, lane = t & 31, w = t >> 5;
    const int kg = w & 3, ih = w >> 2;
    const int gt = t & 127;
    const int barid = 1 + ih;
    const int iL = ih * 32 + lane;

    const float* __restrict__ xg = X + (size_t)b * (II * JJ);
    float* __restrict__ blg = g_bl + (size_t)b * (KK * II);
    const unsigned smbase = (unsigned)__cvta_generic_to_shared(sm);

    {
        const float4* Tg = (const float4*)(g_T + (size_t)b * KK * JJ);
        #pragma unroll
        for (int ee = 0; ee < 4; ++ee)
            ((float4*)Tm)[t + ee * 256] = Tg[t + ee * 256];
    }
    u64 a1[8][2];
    #pragma unroll
    for (int q = 0; q < 8; ++q) { a1[q][0] = 0; a1[q][1] = 0; }

    // preload chunk 0 into buf0 (own group's rows)
    {
        const int ibase = split * ILEN;
        #pragma unroll
        for (int ee = 0; ee < 8; ++ee) {
            const int e4 = gt + ee * 128;
            const int il = ih * 32 + (e4 >> 5), j4 = e4 & 31;
            const unsigned dst = smbase + (unsigned)(il * 128 + ((j4 ^ (il & 31)) << 2)) * 4u;
            asm volatile("cp.async.cg.shared.global [%0], [%1], 16;\n"
                         :: "r"(dst), "l"(xg + (size_t)(ibase + il) * JJ + j4 * 4));
        }
        CP_COMMIT();
    }
    __syncthreads();                            // Tm visible; groups aligned

    for (int ch = 0; ch < NCH; ++ch) {
        const int ibase = split * ILEN + ch * CI;
        const float* xb = sm + ((ch & 1) ? K2_XS1 : K2_XS0);

        CP_WAIT0();
        GBAR(barid);   // chunk data in; prev chunk's GEMM1 done

        if (ch + 1 < NCH) {
            const unsigned boff = ((ch & 1) ? K2_XS0 : K2_XS1) * 4u;
            const float* src = xg + (size_t)(ibase + CI) * JJ;
            #pragma unroll
            for (int ee = 0; ee < 8; ++ee) {
                const int e4 = gt + ee * 128;
                const int il = ih * 32 + (e4 >> 5), j4 = e4 & 31;
                const unsigned dst = smbase + boff + (unsigned)(il * 128 + ((j4 ^ (il & 31)) << 2)) * 4u;
                asm volatile("cp.async.cg.shared.global [%0], [%1], 16;\n"
                             :: "r"(dst), "l"(src + (size_t)il * JJ + j4 * 4));
            }
            CP_COMMIT();
        }
        float blold[8];
        if (trans) {
            #pragma unroll
            for (int q = 0; q < 8; ++q)
                blold[q] = blg[(size_t)(kg * 8 + q) * II + ibase + iL];
        }

        // GEMM2: warp = 8 k x 32 i (lane) x 128 j
        u64 a2[8];
        #pragma unroll
        for (int q = 0; q < 8; ++q) a2[q] = 0;
        {
            const float* xr = xb + iL * 128;
            #pragma unroll 4
            for (int jq = 0; jq < 32; ++jq) {
                const ulonglong2 xv = *(const ulonglong2*)(xr + ((jq ^ lane) << 2));
                #pragma unroll
                for (int q = 0; q < 8; ++q) {
                    const ulonglong2 tq = *(const ulonglong2*)(Tm + (kg * 8 + q) * JJ + jq * 4);
                    FMA2(a2[q], tq.x, xv.x, a2[q]);
                    FMA2(a2[q], tq.y, xv.y, a2[q]);
                }
            }
        }
        float ex[8], ssloc = 0.f;
        #pragma unroll
        for (int q = 0; q < 8; ++q) {
            const float2 f = *(float2*)&a2[q];
            float val = f.x + f.y;
            if (trans) val += blold[q];
            else       blg[(size_t)(kg * 8 + q) * II + ibase + iL] = val;
            ex[q] = __expf(val);
            ssloc += ex[q];
        }
        c2[iL * C2P + 32 + kg] = ssloc;
        GBAR(barid);

        {
            const float4 sp = *(const float4*)(c2 + iL * C2P + 32);
            const float inv = 1.0f / (sp.x + sp.y + sp.z + sp.w);
            *(float4*)(c2 + iL * C2P + kg * 8) =
                make_float4(ex[0] * inv, ex[1] * inv, ex[2] * inv, ex[3] * inv);
            *(float4*)(c2 + iL * C2P + kg * 8 + 4) =
                make_float4(ex[4] * inv, ex[5] * inv, ex[6] * inv, ex[7] * inv);
        }
        GBAR(barid);

        // GEMM1: warp = 8 k x 32 i (own half) x 128 j
        #pragma unroll 2
        for (int ii = 0; ii < 32; ++ii) {
            const int i = ih * 32 + ii;
            const ulonglong2 xv = *(const ulonglong2*)(xb + i * 128 + ((lane ^ ii) << 2));
            const float4 c0 = *(const float4*)(c2 + i * C2P + kg * 8);
            const float4 c1 = *(const float4*)(c2 + i * C2P + kg * 8 + 4);
            u64 cc;
            PACK2(cc, c0.x); FMA2(a1[0][0], cc, xv.x, a1[0][0]); FMA2(a1[0][1], cc, xv.y, a1[0][1]);
            PACK2(cc, c0.y); FMA2(a1[1][0], cc, xv.x, a1[1][0]); FMA2(a1[1][1], cc, xv.y, a1[1][1]);
            PACK2(cc, c0.z); FMA2(a1[2][0], cc, xv.x, a1[2][0]); FMA2(a1[2][1], cc, xv.y, a1[2][1]);
            PACK2(cc, c0.w); FMA2(a1[3][0], cc, xv.x, a1[3][0]); FMA2(a1[3][1], cc, xv.y, a1[3][1]);
            PACK2(cc, c1.x); FMA2(a1[4][0], cc, xv.x, a1[4][0]); FMA2(a1[4][1], cc, xv.y, a1[4][1]);
            PACK2(cc, c1.y); FMA2(a1[5][0], cc, xv.x, a1[5][0]); FMA2(a1[5][1], cc, xv.y, a1[5][1]);
            PACK2(cc, c1.z); FMA2(a1[6][0], cc, xv.x, a1[6][0]); FMA2(a1[6][1], cc, xv.y, a1[6][1]);
            PACK2(cc, c1.w); FMA2(a1[7][0], cc, xv.x, a1[7][0]); FMA2(a1[7][1], cc, xv.y, a1[7][1]);
        }
        // loop-top GBAR orders these reads vs. c2/buffer reuse
    }

    float* yp = g_yp + ((size_t)(b * NSPLIT + split) * 2 + ih) * KK * JJ;
    #pragma unroll
    for (int q = 0; q < 8; ++q)
        *(ulonglong2*)(yp + (kg * 8 + q) * JJ + lane * 4) =
            make_ulonglong2(a1[q][0], a1[q][1]);
}

extern "C" void kernel_launch(void* const* d_in, const int* in_sizes, int n_in,
                              void* d_out, int out_size)
{
    (void)in_sizes; (void)n_in; (void)out_size;
    const float* X = (const float*)d_in[0];   // [128, 1152, 128] f32
    const float* W = (const float*)d_in[1];   // [128, 32, 32] f32
    float* out = (float*)d_out;               // [128, 32, 32] f32

    cudaFuncSetAttribute(kOut, cudaFuncAttributeMaxDynamicSharedMemorySize, KO_SMEM);
    cudaFuncSetAttribute(k2_stream, cudaFuncAttributeMaxDynamicSharedMemorySize, K2_SMEM);

    kG<<<32 + 512, 256>>>(W, X);
    kY<<<dim3(KK, 8), 256>>>(0);
    k2_stream<<<dim3(NSPLIT, BB), 256, K2_SMEM>>>(X, 0);
    kY<<<dim3(KK, 8), 256>>>(1);
    k2_stream<<<dim3(NSPLIT, BB), 256, K2_SMEM>>>(X, 1);
    kOut<<<dim3(KK, 4), 256, KO_SMEM>>>(W, out);
}

// round 13
// speedup vs baseline: 1.4006x; 1.0360x over previous
#include <cuda_runtime.h>

// CapsuleLayer dynamic routing, factored + Gram form, v8.
// X[B=128, I=1152, J=128], W[J=128, K=32, D=32], out V[B=128, K=32, D=32]
//  kG  : G[k] = W_k W_k^T + it0 colsum partials
//  kY  : per (k, 16 batches): y -> z = G y (G cp.async double-buffered) -> T
//        mode1 accumulates T into g_T (Tsum), eliminating the bl scratch:
//        bl_trans1 = X (T0+T1)  since bl starts at 0.
//  k2  : per (split, b): cp.async double-buffered x chunks, two 128-thread
//        groups; GEMM2 -> exp -> norm -> GEMM1. No bl gmem traffic at all.
//  kOut: s = y*W -> squash -> out

#define BB 128
#define II 1152
#define JJ 128
#define KK 32
#define DD 32
#define KD 1024
#define NSPLIT 2
#define ILEN 576
#define CI 64
#define NCH 9
#define C2P 36
#define NYP (NSPLIT*2)
#define YMP 20
#define GCH 16           // G rows per staged chunk in kY

typedef unsigned long long u64;

#define FMA2(d,a,b,c) asm("fma.rn.f32x2 %0, %1, %2, %3;" : "=l"(d) : "l"(a), "l"(b), "l"(c))
#define ADD2(d,a,b)   asm("add.rn.f32x2 %0, %1, %2;" : "=l"(d) : "l"(a), "l"(b))
#define PACK2(d,s)    asm("mov.b64 %0, {%1, %1};" : "=l"(d) : "r"(__float_as_uint(s)))
#define GBAR(id)      asm volatile("bar.sync %0, 128;" :: "r"(id) : "memory")
#define CP_COMMIT()   asm volatile("cp.async.commit_group;\n" ::: "memory")
#define CP_WAIT0()    asm volatile("cp.async.wait_group 0;\n" ::: "memory")
#define CP16(dst,src) asm volatile("cp.async.cg.shared.global [%0], [%1], 16;\n" :: "r"(dst), "l"(src))

__device__ float g_T[(size_t)BB * KK * JJ];             // [b][k][j]
__device__ float g_yp[(size_t)BB * NYP * KK * JJ];      // [b][slot][k][j]
__device__ float g_ycol[(size_t)BB * 4 * JJ];           // [b][p][j]
__device__ float g_G[(size_t)KK * JJ * JJ];             // [k][j'][j]

// ===================== kG: Gram build + it0 colsum =====================
__global__ __launch_bounds__(256)
void kG(const float* __restrict__ W, const float* __restrict__ X)
{
    const int t = threadIdx.x;
    if (blockIdx.x < 32) {
        __shared__ float wsm[JJ * 33];
        const int k = blockIdx.x;
        #pragma unroll
        for (int ee = 0; ee < 16; ++ee) {
            const int idx = t + ee * 256;            // j*32 + d
            wsm[(idx >> 5) * 33 + (idx & 31)] = W[(size_t)(idx >> 5) * KD + k * DD + (idx & 31)];
        }
        __syncthreads();
        const int j = t & 127, half = t >> 7;
        float rj[32];
        #pragma unroll
        for (int d = 0; d < 32; ++d) rj[d] = wsm[j * 33 + d];
        float* Gk = g_G + (size_t)k * (JJ * JJ);
        #pragma unroll 2
        for (int jp = 0; jp < 64; ++jp) {
            const int jpg = half * 64 + jp;
            float acc = 0.f;
            #pragma unroll
            for (int d = 0; d < 32; ++d)
                acc = fmaf(rj[d], wsm[jpg * 33 + d], acc);
            Gk[jpg * JJ + j] = acc;
        }
        return;
    }
    __shared__ ulonglong2 sred[256];
    const int bid = blockIdx.x - 32;
    const int b = bid & 127, p = bid >> 7;
    const int j4 = t & 31, ih = t >> 5;
    const float* xp = X + (size_t)b * (II * JJ) + (size_t)(p * 288 + ih * 36) * JJ + j4 * 4;
    u64 s0 = 0, s1 = 0;
    #pragma unroll 4
    for (int ii = 0; ii < 36; ++ii) {
        ulonglong2 v = *(const ulonglong2*)(xp + (size_t)ii * JJ);
        ADD2(s0, s0, v.x); ADD2(s1, s1, v.y);
    }
    sred[ih * 32 + j4] = make_ulonglong2(s0, s1);
    __syncthreads();
    if (t < 32) {
        u64 a0 = 0, a1 = 0;
        #pragma unroll
        for (int h = 0; h < 8; ++h) {
            ulonglong2 v = sred[h * 32 + t];
            ADD2(a0, a0, v.x); ADD2(a1, a1, v.y);
        }
        ((ulonglong2*)(g_ycol + (size_t)(b * 4 + p) * JJ))[t] = make_ulonglong2(a0, a1);
    }
}

// ===================== kY: y -> z = G y -> scale -> T (accumulating) =====================
__global__ __launch_bounds__(256)
void kY(int mode)                   // 0: y from colsum, T = scl*z ; 1: y from g_yp, T += scl*z
{
    __shared__ float ymt[JJ * YMP];     // [j][b], pitch 20
    __shared__ float Gs[2][GCH * JJ];   // double-buffered G chunks
    __shared__ float ssb[64];
    __shared__ float scl[16];

    const int k = blockIdx.x, b0 = blockIdx.y * 16;
    const int t = threadIdx.x;
    const float* Gk = g_G + (size_t)k * (JJ * JJ);
    const unsigned gs0 = (unsigned)__cvta_generic_to_shared(&Gs[0][0]);
    const unsigned gs1 = (unsigned)__cvta_generic_to_shared(&Gs[1][0]);

    // preload G chunk 0 (8KB = 512 float4, 2 per thread)
    #pragma unroll
    for (int e = 0; e < 2; ++e) {
        const int idx = t + e * 256;
        CP16(gs0 + (unsigned)idx * 16u, (const float4*)Gk + idx);
    }
    CP_COMMIT();

    // stage y transposed: ymt[j][b]
    {
        const int bL = t >> 6, jj = (t & 63) * 2;
        #pragma unroll
        for (int pass = 0; pass < 4; ++pass) {
            const int b = pass * 4 + bL;
            float v0, v1;
            if (mode == 0) {
                const float* yc = g_ycol + (size_t)(b0 + b) * 4 * JJ;
                v0 = (yc[jj]   + yc[128 + jj] + yc[256 + jj] + yc[384 + jj]) * (1.0f / 32.0f);
                v1 = (yc[jj+1] + yc[129 + jj] + yc[257 + jj] + yc[385 + jj]) * (1.0f / 32.0f);
            } else {
                const float* yp = g_yp + (size_t)(b0 + b) * NYP * KK * JJ + (size_t)k * JJ + jj;
                v0 = 0.f; v1 = 0.f;
                #pragma unroll
                for (int s = 0; s < NYP; ++s) {
                    const float2 u = *(const float2*)(yp + (size_t)s * KK * JJ);
                    v0 += u.x; v1 += u.y;
                }
            }
            ymt[jj * YMP + b] = v0;
            ymt[(jj + 1) * YMP + b] = v1;
        }
    }

    // z[b][j], 8 b per thread; G from double-buffered smem
    const int j = t & 127, bh = t >> 7;
    float z[8];
    #pragma unroll
    for (int r = 0; r < 8; ++r) z[r] = 0.f;

    for (int c = 0; c < JJ / GCH; ++c) {
        CP_WAIT0();
        __syncthreads();                 // chunk c in; (c==0: also ymt ready; prev compute done)
        if (c + 1 < JJ / GCH) {
            const unsigned dstb = (c & 1) ? gs0 : gs1;
            const float4* src = (const float4*)(Gk + (c + 1) * GCH * JJ);
            #pragma unroll
            for (int e = 0; e < 2; ++e) {
                const int idx = t + e * 256;
                CP16(dstb + (unsigned)idx * 16u, src + idx);
            }
            CP_COMMIT();
        }
        const float* gb = Gs[c & 1];
        #pragma unroll
        for (int u = 0; u < GCH; ++u) {
            const float g = gb[u * JJ + j];                         // conflict-free
            const int jp = c * GCH + u;
            const float4 y0 = *(const float4*)(ymt + jp * YMP + bh * 8);       // bcast
            const float4 y1 = *(const float4*)(ymt + jp * YMP + bh * 8 + 4);
            z[0] = fmaf(y0.x, g, z[0]); z[1] = fmaf(y0.y, g, z[1]);
            z[2] = fmaf(y0.z, g, z[2]); z[3] = fmaf(y0.w, g, z[3]);
            z[4] = fmaf(y1.x, g, z[4]); z[5] = fmaf(y1.y, g, z[5]);
            z[6] = fmaf(y1.z, g, z[6]); z[7] = fmaf(y1.w, g, z[7]);
        }
    }

    // ss[b] = sum_j y z
    {
        float ssp[8];
        #pragma unroll
        for (int r = 0; r < 8; ++r)
            ssp[r] = ymt[j * YMP + bh * 8 + r] * z[r];
        #pragma unroll
        for (int off = 16; off > 0; off >>= 1) {
            #pragma unroll
            for (int r = 0; r < 8; ++r)
                ssp[r] += __shfl_xor_sync(0xffffffffu, ssp[r], off);
        }
        const int w = t >> 5;
        if ((t & 31) == 0) {
            #pragma unroll
            for (int r = 0; r < 8; ++r)
                ssb[(w & 3) * 16 + bh * 8 + r] = ssp[r];
        }
    }
    __syncthreads();
    if (t < 16) {
        const float ss = ssb[t] + ssb[16 + t] + ssb[32 + t] + ssb[48 + t];
        scl[t] = ss / (1.0f + ss) * rsqrtf(ss + 1e-7f);
    }
    __syncthreads();

    #pragma unroll
    for (int r = 0; r < 8; ++r) {
        const int b = bh * 8 + r;
        const size_t ti = (size_t)(b0 + b) * KK * JJ + (size_t)k * JJ + j;
        float tv = z[r] * scl[b];
        if (mode) tv += g_T[ti];         // Tsum = T0 + T1  (bl = X*Tsum)
        g_T[ti] = tv;
    }
}

// ===================== kOut: s = y*W -> squash -> out =====================
#define KO_W  0                     // 128*33 = 4224
#define KO_Y  4224                  // 32*128 = 4096
#define KO_FLOATS (KO_Y + 4096)
#define KO_SMEM (KO_FLOATS * 4)

__global__ __launch_bounds__(256)
void kOut(const float* __restrict__ W, float* __restrict__ out)
{
    extern __shared__ float sm[];
    float* wsm = sm + KO_W;
    float* ymb = sm + KO_Y;

    const int k = blockIdx.x, b0 = blockIdx.y * 32;
    const int t = threadIdx.x;

    #pragma unroll
    for (int ee = 0; ee < 16; ++ee) {
        const int idx = t + ee * 256;
        wsm[(idx >> 5) * 33 + (idx & 31)] = W[(size_t)(idx >> 5) * KD + k * DD + (idx & 31)];
    }
    {
        const int bL = t >> 6, jj = (t & 63) * 2;
        #pragma unroll
        for (int pass = 0; pass < 8; ++pass) {
            const int b = pass * 4 + bL;
            const float* yp = g_yp + (size_t)(b0 + b) * NYP * KK * JJ + (size_t)k * JJ + jj;
            float v0 = 0.f, v1 = 0.f;
            #pragma unroll
            for (int s = 0; s < NYP; ++s) {
                const float2 u = *(const float2*)(yp + (size_t)s * KK * JJ);
                v0 += u.x; v1 += u.y;
            }
            ymb[b * JJ + jj] = v0;
            ymb[b * JJ + jj + 1] = v1;
        }
    }
    __syncthreads();

    const int b = t >> 3, d0 = t & 7;
    float s4[4] = {0.f, 0.f, 0.f, 0.f};
    #pragma unroll 4
    for (int j = 0; j < JJ; ++j) {
        const float yv = ymb[b * JJ + j];
        #pragma unroll
        for (int q = 0; q < 4; ++q)
            s4[q] = fmaf(yv, wsm[j * 33 + d0 + 8 * q], s4[q]);
    }
    float ssp = s4[0]*s4[0] + s4[1]*s4[1] + s4[2]*s4[2] + s4[3]*s4[3];
    ssp += __shfl_xor_sync(0xffffffffu, ssp, 1, 8);
    ssp += __shfl_xor_sync(0xffffffffu, ssp, 2, 8);
    ssp += __shfl_xor_sync(0xffffffffu, ssp, 4, 8);
    const float scale = ssp / (1.0f + ssp) * rsqrtf(ssp + 1e-7f);
    #pragma unroll
    for (int q = 0; q < 4; ++q)
        out[(size_t)(b0 + b) * KK * DD + k * DD + d0 + 8 * q] = s4[q] * scale;
}

// ===================== k2: cp.async pipelined GEMM2 -> softmax -> GEMM1 =====================
#define K2_XS0 0         // buf0: 8192 f (XOR swizzle)
#define K2_XS1 8192      // buf1: 8192 f
#define K2_TM  16384     // 4096 f
#define K2_C2  20480     // 64*36 = 2304 f
#define K2_FLOATS 22784
#define K2_SMEM (K2_FLOATS * 4)

__global__ __launch_bounds__(256, 2)
void k2_stream(const float* __restrict__ X)
{
    extern __shared__ float sm[];
    float* Tm = sm + K2_TM;
    float* c2 = sm + K2_C2;

    const int b = blockIdx.y, split = blockIdx.x;
    const int t = threadIdx.x, lane = t & 31, w = t >> 5;
    const int kg = w & 3, ih = w >> 2;
    const int gt = t & 127;
    const int barid = 1 + ih;
    const int iL = ih * 32 + lane;

    const float* __restrict__ xg = X + (size_t)b * (II * JJ);
    const unsigned smbase = (unsigned)__cvta_generic_to_shared(sm);

    {
        const float4* Tg = (const float4*)(g_T + (size_t)b * KK * JJ);
        #pragma unroll
        for (int ee = 0; ee < 4; ++ee)
            ((float4*)Tm)[t + ee * 256] = Tg[t + ee * 256];
    }
    u64 a1[8][2];
    #pragma unroll
    for (int q = 0; q < 8; ++q) { a1[q][0] = 0; a1[q][1] = 0; }

    // preload chunk 0 into buf0 (own group's rows)
    {
        const int ibase = split * ILEN;
        #pragma unroll
        for (int ee = 0; ee < 8; ++ee) {
            const int e4 = gt + ee * 128;
            const int il = ih * 32 + (e4 >> 5), j4 = e4 & 31;
            const unsigned dst = smbase + (unsigned)(il * 128 + ((j4 ^ (il & 31)) << 2)) * 4u;
            CP16(dst, xg + (size_t)(ibase + il) * JJ + j4 * 4);
        }
        CP_COMMIT();
    }
    __syncthreads();                            // Tm visible; groups aligned

    for (int ch = 0; ch < NCH; ++ch) {
        const int ibase = split * ILEN + ch * CI;
        const float* xb = sm + ((ch & 1) ? K2_XS1 : K2_XS0);

        CP_WAIT0();
        GBAR(barid);   // chunk data in; prev chunk's GEMM1 done

        if (ch + 1 < NCH) {
            const unsigned boff = ((ch & 1) ? K2_XS0 : K2_XS1) * 4u;
            const float* src = xg + (size_t)(ibase + CI) * JJ;
            #pragma unroll
            for (int ee = 0; ee < 8; ++ee) {
                const int e4 = gt + ee * 128;
                const int il = ih * 32 + (e4 >> 5), j4 = e4 & 31;
                const unsigned dst = smbase + boff + (unsigned)(il * 128 + ((j4 ^ (il & 31)) << 2)) * 4u;
                CP16(dst, src + (size_t)il * JJ + j4 * 4);
            }
            CP_COMMIT();
        }

        // GEMM2: warp = 8 k x 32 i (lane) x 128 j  (logits = X * Tsum, no bl scratch)
        u64 a2[8];
        #pragma unroll
        for (int q = 0; q < 8; ++q) a2[q] = 0;
        {
            const float* xr = xb + iL * 128;
            #pragma unroll 4
            for (int jq = 0; jq < 32; ++jq) {
                const ulonglong2 xv = *(const ulonglong2*)(xr + ((jq ^ lane) << 2));
                #pragma unroll
                for (int q = 0; q < 8; ++q) {
                    const ulonglong2 tq = *(const ulonglong2*)(Tm + (kg * 8 + q) * JJ + jq * 4);
                    FMA2(a2[q], tq.x, xv.x, a2[q]);
                    FMA2(a2[q], tq.y, xv.y, a2[q]);
                }
            }
        }
        float ex[8], ssloc = 0.f;
        #pragma unroll
        for (int q = 0; q < 8; ++q) {
            const float2 f = *(float2*)&a2[q];
            ex[q] = __expf(f.x + f.y);          // |logit| small: max-sub not needed
            ssloc += ex[q];
        }
        c2[iL * C2P + 32 + kg] = ssloc;
        GBAR(barid);

        {
            const float4 sp = *(const float4*)(c2 + iL * C2P + 32);
            const float inv = 1.0f / (sp.x + sp.y + sp.z + sp.w);
            *(float4*)(c2 + iL * C2P + kg * 8) =
                make_float4(ex[0] * inv, ex[1] * inv, ex[2] * inv, ex[3] * inv);
            *(float4*)(c2 + iL * C2P + kg * 8 + 4) =
                make_float4(ex[4] * inv, ex[5] * inv, ex[6] * inv, ex[7] * inv);
        }
        GBAR(barid);

        // GEMM1: warp = 8 k x 32 i (own half) x 128 j
        #pragma unroll 2
        for (int ii = 0; ii < 32; ++ii) {
            const int i = ih * 32 + ii;
            const ulonglong2 xv = *(const ulonglong2*)(xb + i * 128 + ((lane ^ ii) << 2));
            const float4 c0 = *(const float4*)(c2 + i * C2P + kg * 8);
            const float4 c1 = *(const float4*)(c2 + i * C2P + kg * 8 + 4);
            u64 cc;
            PACK2(cc, c0.x); FMA2(a1[0][0], cc, xv.x, a1[0][0]); FMA2(a1[0][1], cc, xv.y, a1[0][1]);
            PACK2(cc, c0.y); FMA2(a1[1][0], cc, xv.x, a1[1][0]); FMA2(a1[1][1], cc, xv.y, a1[1][1]);
            PACK2(cc, c0.z); FMA2(a1[2][0], cc, xv.x, a1[2][0]); FMA2(a1[2][1], cc, xv.y, a1[2][1]);
            PACK2(cc, c0.w); FMA2(a1[3][0], cc, xv.x, a1[3][0]); FMA2(a1[3][1], cc, xv.y, a1[3][1]);
            PACK2(cc, c1.x); FMA2(a1[4][0], cc, xv.x, a1[4][0]); FMA2(a1[4][1], cc, xv.y, a1[4][1]);
            PACK2(cc, c1.y); FMA2(a1[5][0], cc, xv.x, a1[5][0]); FMA2(a1[5][1], cc, xv.y, a1[5][1]);
            PACK2(cc, c1.z); FMA2(a1[6][0], cc, xv.x, a1[6][0]); FMA2(a1[6][1], cc, xv.y, a1[6][1]);
            PACK2(cc, c1.w); FMA2(a1[7][0], cc, xv.x, a1[7][0]); FMA2(a1[7][1], cc, xv.y, a1[7][1]);
        }
        // loop-top GBAR orders these reads vs. c2/buffer reuse
    }

    float* yp = g_yp + ((size_t)(b * NSPLIT + split) * 2 + ih) * KK * JJ;
    #pragma unroll
    for (int q = 0; q < 8; ++q)
        *(ulonglong2*)(yp + (kg * 8 + q) * JJ + lane * 4) =
            make_ulonglong2(a1[q][0], a1[q][1]);
}

extern "C" void kernel_launch(void* const* d_in, const int* in_sizes, int n_in,
                              void* d_out, int out_size)
{
    (void)in_sizes; (void)n_in; (void)out_size;
    const float* X = (const float*)d_in[0];   // [128, 1152, 128] f32
    const float* W = (const float*)d_in[1];   // [128, 32, 32] f32
    float* out = (float*)d_out;               // [128, 32, 32] f32

    cudaFuncSetAttribute(kOut, cudaFuncAttributeMaxDynamicSharedMemorySize, KO_SMEM);
    cudaFuncSetAttribute(k2_stream, cudaFuncAttributeMaxDynamicSharedMemorySize, K2_SMEM);

    kG<<<32 + 512, 256>>>(W, X);
    kY<<<dim3(KK, 8), 256>>>(0);                             // T = T0
    k2_stream<<<dim3(NSPLIT, BB), 256, K2_SMEM>>>(X);        // c1 from X*T0
    kY<<<dim3(KK, 8), 256>>>(1);                             // T = T0 + T1
    k2_stream<<<dim3(NSPLIT, BB), 256, K2_SMEM>>>(X);        // c2 from X*(T0+T1)
    kOut<<<dim3(KK, 4), 256, KO_SMEM>>>(W, out);
}